// round 14
// baseline (speedup 1.0000x reference)
#include <cuda_runtime.h>

// Single-pass inclusive cumsum along leading axis of xs[T, D] (fp32).
// Output: d_out[0:D] = final carry, d_out[D:] = ys[T,D].
//
// Register-staged decoupled lookback, v2:
//  - CTA = 256 threads = 4 row-slices x 64 float4-columns; 8 rows/thread in
//    registers (xs read exactly once). 4 CTAs/SM so barrier/lookback bubbles
//    of one CTA are filled by three others.
//  - slice-3 threads publish CTA aggregate and run a BATCHED epoch-coded
//    per-column lookback (4 statuses per L2 round-trip, no flag reset ->
//    single graph node). ex broadcast via smem; stores straight from regs.

#define THREADS 256
#define C_F4    64             // float4 columns per CTA
#define SLICES  4
#define RPT     8              // rows per thread
#define ROWS    (SLICES * RPT) // 32 rows per chunk
#define LBB     4              // lookback batch
#define MAX_CHUNKS 512
#define MAX_SP4    2048

static __device__ float4 g_agg4[MAX_CHUNKS * MAX_SP4];
static __device__ float4 g_inc4[MAX_CHUNKS * MAX_SP4];
static __device__ int    g_stat[MAX_CHUNKS * MAX_SP4];  // epoch-coded status

__device__ __forceinline__ int ld_acquire(const int* p) {
    int v;
    asm volatile("ld.acquire.gpu.global.b32 %0, [%1];" : "=r"(v) : "l"(p) : "memory");
    return v;
}
__device__ __forceinline__ void st_release(int* p, int v) {
    asm volatile("st.release.gpu.global.b32 [%0], %1;" :: "l"(p), "r"(v) : "memory");
}
__device__ __forceinline__ float4 f4add(float4 a, float4 b) {
    return make_float4(a.x + b.x, a.y + b.y, a.z + b.z, a.w + b.w);
}

__global__ __launch_bounds__(THREADS, 4)
void scan_lookback(const float4* __restrict__ xs4, float4* __restrict__ ys4,
                   float4* __restrict__ carry4,
                   int stride4, int sp4, int T, int chunks) {
    __shared__ float4 sm_tot[SLICES][C_F4];
    __shared__ float4 sm_ex[C_F4];

    const int g   = blockIdx.x;            // column group
    const int c   = blockIdx.y;            // chunk (x fastest in bid order)
    const int t4  = threadIdx.x & (C_F4 - 1);
    const int s   = threadIdx.x >> 6;      // row slice 0..3
    const int gc4 = g * C_F4 + t4;
    const bool act = gc4 < stride4;

    const int row0 = c * ROWS + s * RPT;
    const float4* xp = xs4 + (size_t)row0 * stride4 + gc4;

    // ---- Load 8 rows into registers (xs read exactly once) ----
    float4 v[RPT];
#pragma unroll
    for (int i = 0; i < RPT; ++i) {
        v[i] = make_float4(0.f, 0.f, 0.f, 0.f);
        if (act && row0 + i < T) v[i] = __ldcs(xp + (size_t)i * stride4);
    }
#pragma unroll
    for (int i = 1; i < RPT; ++i) v[i] = f4add(v[i], v[i - 1]);

    sm_tot[s][t4] = v[RPT - 1];
    __syncthreads();

    // exclusive offset of this slice within the chunk
    float4 off = make_float4(0.f, 0.f, 0.f, 0.f);
#pragma unroll
    for (int ss = 0; ss < SLICES - 1; ++ss)
        if (ss < s) off = f4add(off, sm_tot[ss][t4]);

    // ---- Slice-3 threads: publish aggregate + batched lookback ----
    if (s == SLICES - 1) {
        float4 ex = make_float4(0.f, 0.f, 0.f, 0.f);
        if (act) {
            const float4 agg = f4add(off, v[RPT - 1]);
            const size_t lane = (size_t)c * sp4 + gc4;
            const int e = g_stat[lane] / 2 + 1;   // derive launch epoch
            const int v_agg = 2 * e + 1;
            const int v_inc = 2 * e + 2;
            if (c == 0) {
                g_inc4[lane] = agg;
                st_release(&g_stat[lane], v_inc);
            } else {
                g_agg4[lane] = agg;
                st_release(&g_stat[lane], v_agg);

                int p = c - 1;
                for (;;) {
                    const int n = (p + 1 < LBB) ? (p + 1) : LBB;
                    const size_t base = (size_t)p * sp4 + gc4;
                    int st[LBB];
#pragma unroll
                    for (int i = 0; i < LBB; ++i) st[i] = (i < n) ? 0 : v_inc;
                    for (;;) {                     // load n statuses, retry stale
                        bool stale = false;
#pragma unroll
                        for (int i = 0; i < LBB; ++i) {
                            if (i < n && st[i] <= 2 * e) {
                                st[i] = ld_acquire(&g_stat[base - (size_t)i * sp4]);
                                stale |= (st[i] <= 2 * e);
                            }
                        }
                        if (!stale) break;
                        __nanosleep(32);
                    }
                    int stop = -1;                 // nearest inclusive in batch
#pragma unroll
                    for (int i = 0; i < LBB; ++i)
                        if (i < n && stop < 0 && st[i] >= v_inc) stop = i;
                    const int take = (stop >= 0) ? stop : n;
                    float4 a[LBB];
#pragma unroll
                    for (int i = 0; i < LBB; ++i)
                        if (i < take) a[i] = g_agg4[base - (size_t)i * sp4];
                    float4 incv = make_float4(0.f, 0.f, 0.f, 0.f);
                    if (stop >= 0) incv = g_inc4[base - (size_t)stop * sp4];
#pragma unroll
                    for (int i = 0; i < LBB; ++i)
                        if (i < take) ex = f4add(ex, a[i]);
                    if (stop >= 0) { ex = f4add(ex, incv); break; }
                    p -= n;
                }
                g_inc4[lane] = f4add(ex, agg);
                st_release(&g_stat[lane], v_inc);
            }
            if (c == chunks - 1)
                carry4[gc4] = f4add(ex, agg);     // final carry
        }
        sm_ex[t4] = ex;
    }
    __syncthreads();

    // ---- Write out from registers (streaming stores) ----
    if (act) {
        const float4 base = f4add(sm_ex[t4], off);
        float4* yp = ys4 + (size_t)row0 * stride4 + gc4;
#pragma unroll
        for (int i = 0; i < RPT; ++i)
            if (row0 + i < T)
                __stcs(yp + (size_t)i * stride4, f4add(v[i], base));
    }
}

// ---------------------------------------------------------------------------
extern "C" void kernel_launch(void* const* d_in, const int* in_sizes, int n_in,
                              void* d_out, int out_size) {
    const float* xs = (const float*)d_in[0];
    float* out = (float*)d_out;

    const int total = in_sizes[0];          // T * D
    int D = out_size - total;
    if (D <= 0 || total % D != 0) D = 4096;
    const int T = total / D;

    const int stride4 = D / 4;
    const int ngroups = (stride4 + C_F4 - 1) / C_F4;
    const int sp4     = ngroups * C_F4;
    const int chunks  = (T + ROWS - 1) / ROWS;   // 256 for T=8192

    float* carry = out;
    float* ys    = out + D;

    dim3 grid(ngroups, chunks);
    scan_lookback<<<grid, THREADS>>>((const float4*)xs, (float4*)ys,
                                     (float4*)carry, stride4, sp4, T, chunks);
}

// round 15
// speedup vs baseline: 1.1284x; 1.1284x over previous
#include <cuda_runtime.h>

// Single-pass inclusive cumsum along leading axis of xs[T, D] (fp32).
// Output: d_out[0:D] = final carry, d_out[D:] = ys[T,D].
//
// R12 structure (phase A sum + phase B re-read/accumulate/store, per-column
// epoch-coded flags -> single graph node, L2 evict_last pinning) with:
//  - ROWS=32: grid = 1024 CTAs = ~2 waves, so each wave's 64MB working set
//    fits L2 and phase-B re-reads hit
//  - batched lookback walk: 8 predecessor statuses per L2 round-trip.

#define THREADS 256
#define C_F4    256
#define ROWS    32
#define LBB     8              // lookback batch size
#define MAX_CHUNKS 512
#define MAX_SP4    2048

static __device__ float4 g_agg4[MAX_CHUNKS * MAX_SP4];
static __device__ float4 g_inc4[MAX_CHUNKS * MAX_SP4];
static __device__ int    g_stat[MAX_CHUNKS * MAX_SP4];  // epoch-coded status

__device__ __forceinline__ unsigned long long mk_policy_keep() {
    unsigned long long pol;
    asm("createpolicy.fractional.L2::evict_last.b64 %0, 1.0;" : "=l"(pol));
    return pol;
}
__device__ __forceinline__ float4 ldg_keep(const float4* p, unsigned long long pol) {
    float4 v;
    asm volatile("ld.global.L2::cache_hint.v4.f32 {%0,%1,%2,%3}, [%4], %5;"
                 : "=f"(v.x), "=f"(v.y), "=f"(v.z), "=f"(v.w)
                 : "l"(p), "l"(pol));
    return v;
}
__device__ __forceinline__ int ld_acquire(const int* p) {
    int v;
    asm volatile("ld.acquire.gpu.global.b32 %0, [%1];" : "=r"(v) : "l"(p) : "memory");
    return v;
}
__device__ __forceinline__ void st_release(int* p, int v) {
    asm volatile("st.release.gpu.global.b32 [%0], %1;" :: "l"(p), "r"(v) : "memory");
}
__device__ __forceinline__ float4 f4add(float4 a, float4 b) {
    return make_float4(a.x + b.x, a.y + b.y, a.z + b.z, a.w + b.w);
}

__global__ __launch_bounds__(THREADS)
void scan_lookback(const float4* __restrict__ xs4, float4* __restrict__ ys4,
                   float4* __restrict__ carry4,
                   int stride4, int sp4, int T, int chunks, int rows) {
    const int g   = blockIdx.x;            // column group
    const int c   = blockIdx.y;            // chunk (x fastest in bid order)
    const int t4  = threadIdx.x;
    const int gc4 = g * C_F4 + t4;
    if (gc4 >= stride4) return;

    const int row0 = c * rows;
    const int nr   = min(rows, T - row0);
    const float4* xp = xs4 + (size_t)row0 * stride4 + gc4;
    const unsigned long long pol = mk_policy_keep();

    // Derive this launch's epoch from this lane's leftover flag value.
    const size_t lane = (size_t)c * sp4 + gc4;
    const int e = g_stat[lane] / 2 + 1;
    const int v_agg = 2 * e + 1;
    const int v_inc = 2 * e + 2;

    // ---- Phase A: aggregate this chunk's column, pinning xs in L2 ----
    float4 agg = make_float4(0.f, 0.f, 0.f, 0.f);
    {
        int r = 0;
        for (; r + 8 <= nr; r += 8) {
            float4 v0 = ldg_keep(xp + (size_t)(r + 0) * stride4, pol);
            float4 v1 = ldg_keep(xp + (size_t)(r + 1) * stride4, pol);
            float4 v2 = ldg_keep(xp + (size_t)(r + 2) * stride4, pol);
            float4 v3 = ldg_keep(xp + (size_t)(r + 3) * stride4, pol);
            float4 v4 = ldg_keep(xp + (size_t)(r + 4) * stride4, pol);
            float4 v5 = ldg_keep(xp + (size_t)(r + 5) * stride4, pol);
            float4 v6 = ldg_keep(xp + (size_t)(r + 6) * stride4, pol);
            float4 v7 = ldg_keep(xp + (size_t)(r + 7) * stride4, pol);
            agg = f4add(agg, f4add(f4add(v0, v1), f4add(v2, v3)));
            agg = f4add(agg, f4add(f4add(v4, v5), f4add(v6, v7)));
        }
        for (; r < nr; ++r) agg = f4add(agg, ldg_keep(xp + (size_t)r * stride4, pol));
    }

    // ---- Publish + batched per-column lookback (epoch-coded) ----
    float4 ex = make_float4(0.f, 0.f, 0.f, 0.f);
    if (c == 0) {
        g_inc4[lane] = agg;
        st_release(&g_stat[lane], v_inc);
    } else {
        g_agg4[lane] = agg;
        st_release(&g_stat[lane], v_agg);

        int p = c - 1;
        for (;;) {
            const int n = (p + 1 < LBB) ? (p + 1) : LBB;   // walk p..p-n+1
            const size_t base = (size_t)p * sp4 + gc4;
            int st[LBB];
#pragma unroll
            for (int i = 0; i < LBB; ++i) st[i] = (i < n) ? 0 : v_inc;
            for (;;) {                     // load n statuses, retry stale
                bool stale = false;
#pragma unroll
                for (int i = 0; i < LBB; ++i) {
                    if (i < n && st[i] <= 2 * e) {
                        st[i] = ld_acquire(&g_stat[base - (size_t)i * sp4]);
                        stale |= (st[i] <= 2 * e);
                    }
                }
                if (!stale) break;
                __nanosleep(32);
            }
            int stop = -1;                 // nearest inclusive in batch
#pragma unroll
            for (int i = 0; i < LBB; ++i)
                if (i < n && stop < 0 && st[i] >= v_inc) stop = i;
            const int take = (stop >= 0) ? stop : n;
            float4 a[LBB];
#pragma unroll
            for (int i = 0; i < LBB; ++i)
                if (i < take) a[i] = g_agg4[base - (size_t)i * sp4];
            float4 incv = make_float4(0.f, 0.f, 0.f, 0.f);
            if (stop >= 0) incv = g_inc4[base - (size_t)stop * sp4];
#pragma unroll
            for (int i = 0; i < LBB; ++i)
                if (i < take) ex = f4add(ex, a[i]);
            if (stop >= 0) { ex = f4add(ex, incv); break; }
            p -= n;
        }

        g_inc4[lane] = f4add(ex, agg);
        st_release(&g_stat[lane], v_inc);
    }
    if (c == chunks - 1)
        carry4[gc4] = f4add(ex, agg);       // final carry

    // ---- Phase B: re-read tile (L2 hot within wave), accumulate, store ----
    float4* yp = ys4 + (size_t)row0 * stride4 + gc4;
    float4 acc = ex;
    {
        int r = 0;
        for (; r + 8 <= nr; r += 8) {
            float4 v0 = __ldcs(xp + (size_t)(r + 0) * stride4);
            float4 v1 = __ldcs(xp + (size_t)(r + 1) * stride4);
            float4 v2 = __ldcs(xp + (size_t)(r + 2) * stride4);
            float4 v3 = __ldcs(xp + (size_t)(r + 3) * stride4);
            float4 v4 = __ldcs(xp + (size_t)(r + 4) * stride4);
            float4 v5 = __ldcs(xp + (size_t)(r + 5) * stride4);
            float4 v6 = __ldcs(xp + (size_t)(r + 6) * stride4);
            float4 v7 = __ldcs(xp + (size_t)(r + 7) * stride4);
            acc = f4add(acc, v0); __stcs(yp + (size_t)(r + 0) * stride4, acc);
            acc = f4add(acc, v1); __stcs(yp + (size_t)(r + 1) * stride4, acc);
            acc = f4add(acc, v2); __stcs(yp + (size_t)(r + 2) * stride4, acc);
            acc = f4add(acc, v3); __stcs(yp + (size_t)(r + 3) * stride4, acc);
            acc = f4add(acc, v4); __stcs(yp + (size_t)(r + 4) * stride4, acc);
            acc = f4add(acc, v5); __stcs(yp + (size_t)(r + 5) * stride4, acc);
            acc = f4add(acc, v6); __stcs(yp + (size_t)(r + 6) * stride4, acc);
            acc = f4add(acc, v7); __stcs(yp + (size_t)(r + 7) * stride4, acc);
        }
        for (; r < nr; ++r) {
            float4 v = __ldcs(xp + (size_t)r * stride4);
            acc = f4add(acc, v);
            __stcs(yp + (size_t)r * stride4, acc);
        }
    }
}

// ---------------------------------------------------------------------------
extern "C" void kernel_launch(void* const* d_in, const int* in_sizes, int n_in,
                              void* d_out, int out_size) {
    const float* xs = (const float*)d_in[0];
    float* out = (float*)d_out;

    const int total = in_sizes[0];          // T * D
    int D = out_size - total;
    if (D <= 0 || total % D != 0) D = 4096;
    const int T = total / D;

    const int stride4 = D / 4;
    const int ngroups = (stride4 + C_F4 - 1) / C_F4;
    const int sp4     = ngroups * C_F4;

    int rows = ROWS;
    int chunks = (T + rows - 1) / rows;
    while (chunks > MAX_CHUNKS) { rows <<= 1; chunks = (T + rows - 1) / rows; }

    float* carry = out;
    float* ys    = out + D;

    dim3 grid(ngroups, chunks);
    scan_lookback<<<grid, THREADS>>>((const float4*)xs, (float4*)ys,
                                     (float4*)carry, stride4, sp4, T,
                                     chunks, rows);
}

// round 16
// speedup vs baseline: 1.1667x; 1.0339x over previous
#include <cuda_runtime.h>

// Single-pass inclusive cumsum along leading axis of xs[T, D] (fp32).
// Output: d_out[0:D] = final carry, d_out[D:] = ys[T,D].
//
// ROWS=32 (grid = 1024 CTAs = 2 waves; each wave's 64MB fits L2 so phase-B
// re-reads hit), L2 evict_last pinning on phase-A loads, per-column
// EPOCH-CODED flags (no reset -> single graph node), lean SERIAL lookback
// (low register count -> more resident warps; R11/R15 showed batching the
// walk costs more in regs/alu than it saves in latency).

#define THREADS 256
#define C_F4    256
#define ROWS    32
#define MAX_CHUNKS 512
#define MAX_SP4    2048

static __device__ float4 g_agg4[MAX_CHUNKS * MAX_SP4];
static __device__ float4 g_inc4[MAX_CHUNKS * MAX_SP4];
static __device__ int    g_stat[MAX_CHUNKS * MAX_SP4];  // epoch-coded status

__device__ __forceinline__ unsigned long long mk_policy_keep() {
    unsigned long long pol;
    asm("createpolicy.fractional.L2::evict_last.b64 %0, 1.0;" : "=l"(pol));
    return pol;
}
__device__ __forceinline__ float4 ldg_keep(const float4* p, unsigned long long pol) {
    float4 v;
    asm volatile("ld.global.L2::cache_hint.v4.f32 {%0,%1,%2,%3}, [%4], %5;"
                 : "=f"(v.x), "=f"(v.y), "=f"(v.z), "=f"(v.w)
                 : "l"(p), "l"(pol));
    return v;
}
__device__ __forceinline__ int ld_acquire(const int* p) {
    int v;
    asm volatile("ld.acquire.gpu.global.b32 %0, [%1];" : "=r"(v) : "l"(p) : "memory");
    return v;
}
__device__ __forceinline__ void st_release(int* p, int v) {
    asm volatile("st.release.gpu.global.b32 [%0], %1;" :: "l"(p), "r"(v) : "memory");
}
__device__ __forceinline__ float4 f4add(float4 a, float4 b) {
    return make_float4(a.x + b.x, a.y + b.y, a.z + b.z, a.w + b.w);
}

__global__ __launch_bounds__(THREADS)
void scan_lookback(const float4* __restrict__ xs4, float4* __restrict__ ys4,
                   float4* __restrict__ carry4,
                   int stride4, int sp4, int T, int chunks, int rows) {
    const int g   = blockIdx.x;            // column group
    const int c   = blockIdx.y;            // chunk (x fastest in bid order)
    const int t4  = threadIdx.x;
    const int gc4 = g * C_F4 + t4;
    if (gc4 >= stride4) return;

    const int row0 = c * rows;
    const int nr   = min(rows, T - row0);
    const float4* xp = xs4 + (size_t)row0 * stride4 + gc4;
    const unsigned long long pol = mk_policy_keep();

    // Derive this launch's epoch from this lane's leftover flag value.
    const size_t lane = (size_t)c * sp4 + gc4;
    const int e = g_stat[lane] / 2 + 1;
    const int v_agg = 2 * e + 1;
    const int v_inc = 2 * e + 2;

    // ---- Phase A: aggregate this chunk's column, pinning xs in L2 ----
    float4 agg = make_float4(0.f, 0.f, 0.f, 0.f);
    {
        int r = 0;
        for (; r + 8 <= nr; r += 8) {
            float4 v0 = ldg_keep(xp + (size_t)(r + 0) * stride4, pol);
            float4 v1 = ldg_keep(xp + (size_t)(r + 1) * stride4, pol);
            float4 v2 = ldg_keep(xp + (size_t)(r + 2) * stride4, pol);
            float4 v3 = ldg_keep(xp + (size_t)(r + 3) * stride4, pol);
            float4 v4 = ldg_keep(xp + (size_t)(r + 4) * stride4, pol);
            float4 v5 = ldg_keep(xp + (size_t)(r + 5) * stride4, pol);
            float4 v6 = ldg_keep(xp + (size_t)(r + 6) * stride4, pol);
            float4 v7 = ldg_keep(xp + (size_t)(r + 7) * stride4, pol);
            agg = f4add(agg, f4add(f4add(v0, v1), f4add(v2, v3)));
            agg = f4add(agg, f4add(f4add(v4, v5), f4add(v6, v7)));
        }
        for (; r < nr; ++r) agg = f4add(agg, ldg_keep(xp + (size_t)r * stride4, pol));
    }

    // ---- Publish + serial per-column lookback (epoch-coded) ----
    float4 ex = make_float4(0.f, 0.f, 0.f, 0.f);
    if (c == 0) {
        g_inc4[lane] = agg;
        st_release(&g_stat[lane], v_inc);
    } else {
        g_agg4[lane] = agg;
        st_release(&g_stat[lane], v_agg);
        int p = c - 1;
        for (;;) {
            const size_t pl = (size_t)p * sp4 + gc4;
            int s = ld_acquire(&g_stat[pl]);
            while (s <= 2 * e) { __nanosleep(32); s = ld_acquire(&g_stat[pl]); }
            if (s >= v_inc) { ex = f4add(ex, g_inc4[pl]); break; }
            ex = f4add(ex, g_agg4[pl]);     // s == v_agg
            --p;
        }
        g_inc4[lane] = f4add(ex, agg);
        st_release(&g_stat[lane], v_inc);
    }
    if (c == chunks - 1)
        carry4[gc4] = f4add(ex, agg);       // final carry

    // ---- Phase B: re-read tile (L2 hot within wave), accumulate, store ----
    float4* yp = ys4 + (size_t)row0 * stride4 + gc4;
    float4 acc = ex;
    {
        int r = 0;
        for (; r + 8 <= nr; r += 8) {
            float4 v0 = __ldcs(xp + (size_t)(r + 0) * stride4);
            float4 v1 = __ldcs(xp + (size_t)(r + 1) * stride4);
            float4 v2 = __ldcs(xp + (size_t)(r + 2) * stride4);
            float4 v3 = __ldcs(xp + (size_t)(r + 3) * stride4);
            float4 v4 = __ldcs(xp + (size_t)(r + 4) * stride4);
            float4 v5 = __ldcs(xp + (size_t)(r + 5) * stride4);
            float4 v6 = __ldcs(xp + (size_t)(r + 6) * stride4);
            float4 v7 = __ldcs(xp + (size_t)(r + 7) * stride4);
            acc = f4add(acc, v0); __stcs(yp + (size_t)(r + 0) * stride4, acc);
            acc = f4add(acc, v1); __stcs(yp + (size_t)(r + 1) * stride4, acc);
            acc = f4add(acc, v2); __stcs(yp + (size_t)(r + 2) * stride4, acc);
            acc = f4add(acc, v3); __stcs(yp + (size_t)(r + 3) * stride4, acc);
            acc = f4add(acc, v4); __stcs(yp + (size_t)(r + 4) * stride4, acc);
            acc = f4add(acc, v5); __stcs(yp + (size_t)(r + 5) * stride4, acc);
            acc = f4add(acc, v6); __stcs(yp + (size_t)(r + 6) * stride4, acc);
            acc = f4add(acc, v7); __stcs(yp + (size_t)(r + 7) * stride4, acc);
        }
        for (; r < nr; ++r) {
            float4 v = __ldcs(xp + (size_t)r * stride4);
            acc = f4add(acc, v);
            __stcs(yp + (size_t)r * stride4, acc);
        }
    }
}

// ---------------------------------------------------------------------------
extern "C" void kernel_launch(void* const* d_in, const int* in_sizes, int n_in,
                              void* d_out, int out_size) {
    const float* xs = (const float*)d_in[0];
    float* out = (float*)d_out;

    const int total = in_sizes[0];          // T * D
    int D = out_size - total;
    if (D <= 0 || total % D != 0) D = 4096;
    const int T = total / D;

    const int stride4 = D / 4;
    const int ngroups = (stride4 + C_F4 - 1) / C_F4;
    const int sp4     = ngroups * C_F4;

    int rows = ROWS;
    int chunks = (T + rows - 1) / rows;
    while (chunks > MAX_CHUNKS) { rows <<= 1; chunks = (T + rows - 1) / rows; }

    float* carry = out;
    float* ys    = out + D;

    dim3 grid(ngroups, chunks);
    scan_lookback<<<grid, THREADS>>>((const float4*)xs, (float4*)ys,
                                     (float4*)carry, stride4, sp4, T,
                                     chunks, rows);
}